// round 9
// baseline (speedup 1.0000x reference)
#include <cuda_runtime.h>
#include <cuda_bf16.h>
#include <stdint.h>

#define HID   2048
#define INTER 8192
#define NEXP  8
#define NTOK  16384
#define LN_EPS 1e-5f

// up/down GEMM tiling: 256x128 CTA tile, 16 warps of 32x64 (8Mx2N), BK=64
#define BM 256
#define BN 128
#define BK 64
#define NSTAGES 3
#define A_BYTES (BM * 128)                 // 32 KB
#define B_BYTES (BN * 128)                 // 16 KB
#define STG_BYTES (A_BYTES + B_BYTES)      // 48 KB
#define SMEM_TOTAL (NSTAGES * STG_BYTES)   // 144 KB

// expert GEMM (unchanged from R7): 128x128, BK=32, fused 4-operand, 3 stages
#define EBM 128
#define EBK 32
#define ESTG (4 * EBM * 64)                // 32 KB
#define ESMEM_TOTAL (3 * ESTG)             // 96 KB

// ---------------- scratch (device globals, allocation-free) ----------------
__device__ __align__(16) __nv_bfloat16 g_xh [(size_t)NTOK * HID];
__device__ __align__(16) __nv_bfloat16 g_xl [(size_t)NTOK * HID];
__device__ __align__(16) __nv_bfloat16 g_uwT[(size_t)INTER * HID];   // up_w^T
__device__ __align__(16) __nv_bfloat16 g_dwT[(size_t)HID * INTER];   // down_w^T
__device__ __align__(16) __nv_bfloat16 g_ewTh[(size_t)HID * HID];    // expert_w^T hi
__device__ __align__(16) __nv_bfloat16 g_ewTl[(size_t)HID * HID];    // expert_w^T lo
__device__ __align__(16) __nv_bfloat16 g_h  [(size_t)NTOK * INTER];  // relu(x@up)^2
__device__ float g_scale[NTOK];

// ---------------- PTX helpers (compute_103-safe) ----------------
__device__ __forceinline__ uint32_t smem_u32(const void* p) {
    uint32_t a;
    asm("{ .reg .u64 t; cvta.to.shared.u64 t, %1; cvt.u32.u64 %0, t; }" : "=r"(a) : "l"(p));
    return a;
}
__device__ __forceinline__ void cp_async16(uint32_t s, const void* g) {
    asm volatile("cp.async.cg.shared.global [%0], [%1], 16;" :: "r"(s), "l"(g) : "memory");
}
__device__ __forceinline__ void cp_commit() { asm volatile("cp.async.commit_group;" ::: "memory"); }
template <int N> __device__ __forceinline__ void cp_wait() {
    asm volatile("cp.async.wait_group %0;" :: "n"(N) : "memory");
}
#define LDSM4(R, addr)                                                         \
    asm volatile("ldmatrix.sync.aligned.m8n8.x4.shared.b16 {%0,%1,%2,%3}, [%4];" \
        : "=r"((R)[0]), "=r"((R)[1]), "=r"((R)[2]), "=r"((R)[3]) : "r"(addr))

__device__ __forceinline__ void mma_bf16(float* d, const uint32_t* a,
                                         uint32_t b0, uint32_t b1) {
    asm volatile(
        "mma.sync.aligned.m16n8k16.row.col.f32.bf16.bf16.f32 "
        "{%0,%1,%2,%3}, {%4,%5,%6,%7}, {%8,%9}, {%0,%1,%2,%3};"
        : "+f"(d[0]), "+f"(d[1]), "+f"(d[2]), "+f"(d[3])
        : "r"(a[0]), "r"(a[1]), "r"(a[2]), "r"(a[3]), "r"(b0), "r"(b1));
}

// ---------------------------------------------------------------------------
// up/down bf16 GEMM: D[256,128] = A[256,K] @ B^T (B stored [N,K] K-major).
// 16 warps, 8x2 grid of 32x64 warp tiles. BK=64, 3-stage cp.async pipeline.
// MODE 0: up     A=g_xh, B=g_uwT, out -> g_h (bf16, relu^2)
// MODE 1: down   A=g_h,  B=g_dwT, out: C += D
// ---------------------------------------------------------------------------
template <int MODE>
__global__ __launch_bounds__(512, 1) void gemm_tc(float* __restrict__ C)
{
    constexpr int K  = (MODE == 1) ? INTER : HID;
    constexpr int KT = K / BK;

    extern __shared__ char smem[];
    const uint32_t sb = smem_u32(smem);

    const int tid  = threadIdx.x;
    const int wid  = tid >> 5;
    const int lane = tid & 31;
    const int wm   = wid & 7;          // 8 warps along M (32 rows each)
    const int wn   = wid >> 3;         // 2 warps along N (64 cols each)
    const int mBase = blockIdx.y * BM;
    const int nBase = blockIdx.x * BN;

    // loader: 512 threads; A = 2048 16B lines (4/thr), B = 1024 lines (2/thr)
    const int lrow = tid >> 3;         // 0..63
    const int lseg = tid & 7;
    const uint32_t lsw = (uint32_t)((lseg ^ (lrow & 7)) << 4);

    auto load_chunk = [&](int q) {
        const __nv_bfloat16 *Ap = (MODE == 0) ? g_xh : g_h;
        const __nv_bfloat16 *Bp = (MODE == 0) ? g_uwT : g_dwT;
        const uint32_t base = sb + (q % NSTAGES) * STG_BYTES;
        const size_t k0 = (size_t)q * BK + lseg * 8;
#pragma unroll
        for (int i = 0; i < 4; i++) {   // A rows: lrow + {0,64,128,192}
            const int row = lrow + i * 64;
            cp_async16(base + row * 128 + lsw,
                       Ap + (size_t)(mBase + row) * K + k0);
        }
#pragma unroll
        for (int i = 0; i < 2; i++) {   // B rows: lrow + {0,64}
            const int row = lrow + i * 64;
            cp_async16(base + A_BYTES + row * 128 + lsw,
                       Bp + (size_t)(nBase + row) * K + k0);
        }
    };

    float acc[2][8][4];
#pragma unroll
    for (int i = 0; i < 2; i++)
#pragma unroll
        for (int j = 0; j < 8; j++)
#pragma unroll
            for (int v = 0; v < 4; v++) acc[i][j][v] = 0.f;

    const int g  = lane >> 3;
    const int r8 = lane & 7;
    const int rowA0 = wm * 32 + r8 + (g & 1) * 8;
    const int rowB0 = wn * 64 + r8 + (g & 1) * 8;
    const int segHi = g >> 1;

    load_chunk(0); cp_commit();
    load_chunk(1); cp_commit();

    for (int c = 0; c < KT; ++c) {
        cp_wait<1>();
        __syncthreads();
        if (c + 2 < KT) load_chunk(c + 2);
        cp_commit();

        const uint32_t aB = sb + (c % NSTAGES) * STG_BYTES;
        const uint32_t bB = aB + A_BYTES;
#pragma unroll
        for (int k16 = 0; k16 < 4; k16++) {
            const int seg = k16 * 2 + segHi;
            uint32_t A0[4], A1[4], Bf[4][4];
            {
                const int row = rowA0;
                LDSM4(A0, aB + row * 128 + ((seg ^ (row & 7)) << 4));
            }
            {
                const int row = rowA0 + 16;
                LDSM4(A1, aB + row * 128 + ((seg ^ (row & 7)) << 4));
            }
#pragma unroll
            for (int bt = 0; bt < 4; bt++) {
                const int row = rowB0 + bt * 16;
                LDSM4(Bf[bt], bB + row * 128 + ((seg ^ (row & 7)) << 4));
            }
#pragma unroll
            for (int nj = 0; nj < 8; nj++) {
                const uint32_t b0 = Bf[nj >> 1][nj & 1];
                const uint32_t b1 = Bf[nj >> 1][2 + (nj & 1)];
                mma_bf16(acc[0][nj], A0, b0, b1);
                mma_bf16(acc[1][nj], A1, b0, b1);
            }
        }
    }

    // ---- epilogue ----
    const int rl = lane >> 2;
    const int cl = (lane & 3) * 2;
#pragma unroll
    for (int mi = 0; mi < 2; mi++) {
        const int r0 = mBase + wm * 32 + mi * 16 + rl;
#pragma unroll
        for (int nj = 0; nj < 8; nj++) {
            const int cc = nBase + wn * 64 + nj * 8 + cl;
            const float* d = acc[mi][nj];
            if (MODE == 0) {
                float a0 = d[0] > 0.f ? d[0] * d[0] : 0.f;
                float a1 = d[1] > 0.f ? d[1] * d[1] : 0.f;
                float a2 = d[2] > 0.f ? d[2] * d[2] : 0.f;
                float a3 = d[3] > 0.f ? d[3] * d[3] : 0.f;
                __nv_bfloat162 p0 = __floats2bfloat162_rn(a0, a1);
                __nv_bfloat162 p1 = __floats2bfloat162_rn(a2, a3);
                *(uint32_t*)(g_h + (size_t)r0 * INTER + cc)       = *(uint32_t*)&p0;
                *(uint32_t*)(g_h + (size_t)(r0 + 8) * INTER + cc) = *(uint32_t*)&p1;
            } else {
                float2* p0 = (float2*)(C + (size_t)r0 * HID + cc);
                float2* p1 = (float2*)(C + (size_t)(r0 + 8) * HID + cc);
                float2 v0 = *p0, v1 = *p1;
                v0.x += d[0]; v0.y += d[1];
                v1.x += d[2]; v1.y += d[3];
                *p0 = v0; *p1 = v1;
            }
        }
    }
}

// ---------------------------------------------------------------------------
// Expert GEMM, fused split-bf16 (128x128, unchanged from R7): per K-chunk
// (BK=32) load {xh, xl, wh, wl} once; acc += xh*wh + xl*wh + xh*wl.
// C = acc * g_scale[row].
// ---------------------------------------------------------------------------
__global__ __launch_bounds__(256, 2) void gemm_expert(float* __restrict__ C)
{
    constexpr int K  = HID;
    constexpr int KT = K / EBK;            // 64

    extern __shared__ char smem[];
    const uint32_t sb = smem_u32(smem);

    const int tid  = threadIdx.x;
    const int wid  = tid >> 5;
    const int lane = tid & 31;
    const int wm   = wid & 3;
    const int wn   = wid >> 2;
    const int mBase = blockIdx.y * EBM;
    const int nBase = blockIdx.x * EBM;

    const int lrow = tid >> 2;             // 0..63
    const int lseg = tid & 3;

    auto load_chunk = [&](int q) {
        const uint32_t base = sb + (q % 3) * ESTG;
        const size_t k0 = (size_t)q * EBK + lseg * 8;
#pragma unroll
        for (int i = 0; i < 2; i++) {
            const int row = lrow + i * 64;
            const uint32_t sw = (uint32_t)(row * 64 + ((lseg ^ ((row >> 1) & 3)) << 4));
            const size_t aoff = (size_t)(mBase + row) * K + k0;
            const size_t boff = (size_t)(nBase + row) * K + k0;
            cp_async16(base + sw,          g_xh   + aoff);
            cp_async16(base + 8192 + sw,   g_xl   + aoff);
            cp_async16(base + 16384 + sw,  g_ewTh + boff);
            cp_async16(base + 24576 + sw,  g_ewTl + boff);
        }
    };

    float acc[2][8][4];
#pragma unroll
    for (int i = 0; i < 2; i++)
#pragma unroll
        for (int j = 0; j < 8; j++)
#pragma unroll
            for (int v = 0; v < 4; v++) acc[i][j][v] = 0.f;

    const int g  = lane >> 3;
    const int r8 = lane & 7;
    const int rowA0 = wm * 32 + r8 + (g & 1) * 8;
    const int rowB0 = wn * 64 + r8 + (g & 1) * 8;
    const int segHi = g >> 1;

    load_chunk(0); cp_commit();
    load_chunk(1); cp_commit();

    for (int c = 0; c < KT; ++c) {
        cp_wait<1>();
        __syncthreads();
        if (c + 2 < KT) load_chunk(c + 2);
        cp_commit();

        const uint32_t base = sb + (c % 3) * ESTG;
#pragma unroll
        for (int k16 = 0; k16 < 2; k16++) {
            const int seg = k16 * 2 + segHi;        // 0..3
            uint32_t XH0[4], XH1[4], XL0[4], XL1[4], Bf[4][4];
            {
                const int row = rowA0;
                const uint32_t off = row * 64 + ((seg ^ ((row >> 1) & 3)) << 4);
                LDSM4(XH0, base + off);
                LDSM4(XL0, base + 8192 + off);
            }
            {
                const int row = rowA0 + 16;
                const uint32_t off = row * 64 + ((seg ^ ((row >> 1) & 3)) << 4);
                LDSM4(XH1, base + off);
                LDSM4(XL1, base + 8192 + off);
            }
#pragma unroll
            for (int bt = 0; bt < 4; bt++) {
                const int row = rowB0 + bt * 16;
                LDSM4(Bf[bt], base + 16384 + row * 64 + ((seg ^ ((row >> 1) & 3)) << 4));
            }
#pragma unroll
            for (int nj = 0; nj < 8; nj++) {
                const uint32_t b0 = Bf[nj >> 1][nj & 1];
                const uint32_t b1 = Bf[nj >> 1][2 + (nj & 1)];
                mma_bf16(acc[0][nj], XH0, b0, b1);
                mma_bf16(acc[1][nj], XH1, b0, b1);
                mma_bf16(acc[0][nj], XL0, b0, b1);
                mma_bf16(acc[1][nj], XL1, b0, b1);
            }
#pragma unroll
            for (int bt = 0; bt < 4; bt++) {
                const int row = rowB0 + bt * 16;
                LDSM4(Bf[bt], base + 24576 + row * 64 + ((seg ^ ((row >> 1) & 3)) << 4));
            }
#pragma unroll
            for (int nj = 0; nj < 8; nj++) {
                const uint32_t b0 = Bf[nj >> 1][nj & 1];
                const uint32_t b1 = Bf[nj >> 1][2 + (nj & 1)];
                mma_bf16(acc[0][nj], XH0, b0, b1);
                mma_bf16(acc[1][nj], XH1, b0, b1);
            }
        }
    }

    // ---- epilogue: C = acc * scale[row] ----
    const int rl = lane >> 2;
    const int cl = (lane & 3) * 2;
#pragma unroll
    for (int mi = 0; mi < 2; mi++) {
        const int r0 = mBase + wm * 32 + mi * 16 + rl;
        const float s0 = g_scale[r0];
        const float s8 = g_scale[r0 + 8];
#pragma unroll
        for (int nj = 0; nj < 8; nj++) {
            const int cc = nBase + wn * 64 + nj * 8 + cl;
            const float* d = acc[mi][nj];
            *(float2*)(C + (size_t)r0 * HID + cc)       = make_float2(d[0] * s0, d[1] * s0);
            *(float2*)(C + (size_t)(r0 + 8) * HID + cc) = make_float2(d[2] * s8, d[3] * s8);
        }
    }
}

// ---------------------------------------------------------------------------
// x -> hi/lo bf16 split
// ---------------------------------------------------------------------------
__global__ __launch_bounds__(256) void cvt_x_kernel(const float* __restrict__ x)
{
    const size_t i = ((size_t)blockIdx.x * 256 + threadIdx.x) * 4;
    float4 v = *(const float4*)(x + i);
    __nv_bfloat16 h[4], l[4];
#pragma unroll
    for (int j = 0; j < 4; j++) {
        float f = (&v.x)[j];
        h[j] = __float2bfloat16_rn(f);
        l[j] = __float2bfloat16_rn(f - __bfloat162float(h[j]));
    }
    *(uint2*)(g_xh + i) = *(uint2*)h;
    *(uint2*)(g_xl + i) = *(uint2*)l;
}

// ---------------------------------------------------------------------------
// transpose + bf16 convert: dst[c][r] = bf16(src[r][c])
// WHICH 0: g_uwT  1: g_dwT  2: g_ewTh/g_ewTl split
// ---------------------------------------------------------------------------
template <int WHICH>
__global__ __launch_bounds__(256) void trans_cvt_kernel(const float* __restrict__ src, int R, int C)
{
    __shared__ float t[32][33];
    const int bx = blockIdx.x * 32, by = blockIdx.y * 32;
    const int tx = threadIdx.x & 31, ty = threadIdx.x >> 5;
#pragma unroll
    for (int j = 0; j < 32; j += 8)
        t[ty + j][tx] = src[(size_t)(by + ty + j) * C + bx + tx];
    __syncthreads();
#pragma unroll
    for (int j = 0; j < 32; j += 8) {
        const float v = t[tx][ty + j];
        const __nv_bfloat16 h = __float2bfloat16_rn(v);
        const size_t o = (size_t)(bx + ty + j) * R + by + tx;
        if (WHICH == 0) g_uwT[o] = h;
        else if (WHICH == 1) g_dwT[o] = h;
        else {
            g_ewTh[o] = h;
            g_ewTl[o] = __float2bfloat16_rn(v - __bfloat162float(h));
        }
    }
}

// ---------------------------------------------------------------------------
// Routing: scale = sum of top-2 of x @ gate_w (fp32)
// ---------------------------------------------------------------------------
__global__ __launch_bounds__(256) void routing_kernel(
    const float* __restrict__ x, const float* __restrict__ gate_w)
{
    __shared__ float xs[8][32][33];
    __shared__ float gws[256];
    const int w = threadIdx.x >> 5, lane = threadIdx.x & 31;
    const int t0 = blockIdx.x * 256;
    float acc[NEXP];
#pragma unroll
    for (int e = 0; e < NEXP; e++) acc[e] = 0.f;
    for (int c = 0; c < HID / 32; ++c) {
        const int k0 = c * 32;
#pragma unroll 8
        for (int r = 0; r < 32; ++r)
            xs[w][r][lane] = x[(size_t)(t0 + w * 32 + r) * HID + k0 + lane];
        gws[threadIdx.x] = gate_w[c * 256 + threadIdx.x];
        __syncthreads();
#pragma unroll
        for (int kk = 0; kk < 32; ++kk) {
            const float xv = xs[w][lane][kk];
            const float* g = &gws[kk * NEXP];
#pragma unroll
            for (int e = 0; e < NEXP; e++) acc[e] += xv * g[e];
        }
        __syncthreads();
    }
    float m1 = -1e30f, m2 = -1e30f;
#pragma unroll
    for (int e = 0; e < NEXP; e++) {
        const float v = acc[e];
        if (v > m1) { m2 = m1; m1 = v; } else if (v > m2) { m2 = v; }
    }
    g_scale[t0 + w * 32 + lane] = m1 + m2;
}

// ---------------------------------------------------------------------------
// LayerNorm in place
// ---------------------------------------------------------------------------
__global__ __launch_bounds__(256) void ln_kernel(
    float* __restrict__ y, const float* __restrict__ gamma, const float* __restrict__ beta)
{
    __shared__ float ssum[8], ssum2[8];
    float* row = y + (size_t)blockIdx.x * HID;
    const int base = threadIdx.x * 8;
    float4 v0 = *(float4*)(row + base);
    float4 v1 = *(float4*)(row + base + 4);
    float vals[8] = {v0.x, v0.y, v0.z, v0.w, v1.x, v1.y, v1.z, v1.w};
    float s = 0.f, s2 = 0.f;
#pragma unroll
    for (int i = 0; i < 8; i++) { s += vals[i]; s2 += vals[i] * vals[i]; }
#pragma unroll
    for (int off = 16; off > 0; off >>= 1) {
        s  += __shfl_xor_sync(0xffffffff, s,  off);
        s2 += __shfl_xor_sync(0xffffffff, s2, off);
    }
    const int warp = threadIdx.x >> 5, lane = threadIdx.x & 31;
    if (lane == 0) { ssum[warp] = s; ssum2[warp] = s2; }
    __syncthreads();
    s = 0.f; s2 = 0.f;
#pragma unroll
    for (int i = 0; i < 8; i++) { s += ssum[i]; s2 += ssum2[i]; }
    const float mu = s * (1.f / HID);
    const float rstd = rsqrtf(s2 * (1.f / HID) - mu * mu + LN_EPS);
    float4 g0 = *(const float4*)(gamma + base);
    float4 g1 = *(const float4*)(gamma + base + 4);
    float4 b0 = *(const float4*)(beta + base);
    float4 b1 = *(const float4*)(beta + base + 4);
    float gs[8] = {g0.x, g0.y, g0.z, g0.w, g1.x, g1.y, g1.z, g1.w};
    float bs[8] = {b0.x, b0.y, b0.z, b0.w, b1.x, b1.y, b1.z, b1.w};
    float o[8];
#pragma unroll
    for (int i = 0; i < 8; i++) o[i] = (vals[i] - mu) * rstd * gs[i] + bs[i];
    *(float4*)(row + base)     = make_float4(o[0], o[1], o[2], o[3]);
    *(float4*)(row + base + 4) = make_float4(o[4], o[5], o[6], o[7]);
}

// ---------------------------------------------------------------------------
extern "C" void kernel_launch(void* const* d_in, const int* in_sizes, int n_in,
                              void* d_out, int out_size)
{
    const float* x        = (const float*)d_in[0];
    const float* gate_w   = (const float*)d_in[1];
    const float* up_w     = (const float*)d_in[2];
    const float* down_w   = (const float*)d_in[3];
    const float* expert_w = (const float*)d_in[4];
    const float* gamma    = (const float*)d_in[5];
    const float* beta     = (const float*)d_in[6];
    float* out = (float*)d_out;

    static bool attr_done = false;
    if (!attr_done) {
        cudaFuncSetAttribute(gemm_tc<0>, cudaFuncAttributeMaxDynamicSharedMemorySize, SMEM_TOTAL);
        cudaFuncSetAttribute(gemm_tc<1>, cudaFuncAttributeMaxDynamicSharedMemorySize, SMEM_TOTAL);
        cudaFuncSetAttribute(gemm_expert, cudaFuncAttributeMaxDynamicSharedMemorySize, ESMEM_TOTAL);
        attr_done = true;
    }

    // operand conversions
    cvt_x_kernel<<<(NTOK * HID) / 1024, 256>>>(x);
    trans_cvt_kernel<0><<<dim3(INTER / 32, HID / 32), 256>>>(up_w,     HID,   INTER);
    trans_cvt_kernel<1><<<dim3(HID / 32, INTER / 32), 256>>>(down_w,   INTER, HID);
    trans_cvt_kernel<2><<<dim3(HID / 32, HID / 32),   256>>>(expert_w, HID,   HID);
    // routing (fp32)
    routing_kernel<<<NTOK / 256, 256>>>(x, gate_w);
    // expert (fused split-bf16): out = scale * (x @ expert_w)
    gemm_expert<<<dim3(HID / EBM, NTOK / EBM), 256, ESMEM_TOTAL>>>(out);
    // up: g_h = relu(x @ up_w)^2
    gemm_tc<0><<<dim3(INTER / BN, NTOK / BM), 512, SMEM_TOTAL>>>(nullptr);
    // down: out += g_h @ down_w
    gemm_tc<1><<<dim3(HID / BN, NTOK / BM), 512, SMEM_TOTAL>>>(out);
    // layernorm
    ln_kernel<<<NTOK, 256>>>(out, gamma, beta);
}

// round 10
// speedup vs baseline: 1.1606x; 1.1606x over previous
#include <cuda_runtime.h>
#include <cuda_bf16.h>
#include <stdint.h>

#define HID   2048
#define INTER 8192
#define NEXP  8
#define NTOK  16384
#define LN_EPS 1e-5f

// up/down GEMM tiling: 128x128 CTA tile, 8 warps of 32x64 (4Mx2N), BK=64
#define BM 128
#define BN 128
#define BK 64
#define NSTAGES 3
#define STG_BYTES (2 * BM * 128)           // A 16 KB + B 16 KB
#define SMEM_TOTAL (NSTAGES * STG_BYTES)   // 96 KB

// expert GEMM (tf32): 128x128 CTA tile, BK=32 fp32 (128B rows), 3 stages
#define EBK 32
#define ESTG (2 * BM * 128)                // A 16 KB + B 16 KB
#define ESMEM_TOTAL (3 * ESTG)             // 96 KB

// ---------------- scratch (device globals, allocation-free) ----------------
__device__ __align__(16) __nv_bfloat16 g_xh [(size_t)NTOK * HID];
__device__ __align__(16) __nv_bfloat16 g_uwT[(size_t)INTER * HID];   // up_w^T
__device__ __align__(16) __nv_bfloat16 g_dwT[(size_t)HID * INTER];   // down_w^T
__device__ __align__(16) float          g_ewT[(size_t)HID * HID];    // expert_w^T (tf32-rounded fp32)
__device__ __align__(16) __nv_bfloat16 g_h  [(size_t)NTOK * INTER];  // relu(x@up)^2
__device__ float g_scale[NTOK];

// ---------------- PTX helpers (compute_103-safe) ----------------
__device__ __forceinline__ uint32_t smem_u32(const void* p) {
    uint32_t a;
    asm("{ .reg .u64 t; cvta.to.shared.u64 t, %1; cvt.u32.u64 %0, t; }" : "=r"(a) : "l"(p));
    return a;
}
__device__ __forceinline__ void cp_async16(uint32_t s, const void* g) {
    asm volatile("cp.async.cg.shared.global [%0], [%1], 16;" :: "r"(s), "l"(g) : "memory");
}
__device__ __forceinline__ void cp_commit() { asm volatile("cp.async.commit_group;" ::: "memory"); }
template <int N> __device__ __forceinline__ void cp_wait() {
    asm volatile("cp.async.wait_group %0;" :: "n"(N) : "memory");
}
#define LDSM4(R, addr)                                                         \
    asm volatile("ldmatrix.sync.aligned.m8n8.x4.shared.b16 {%0,%1,%2,%3}, [%4];" \
        : "=r"((R)[0]), "=r"((R)[1]), "=r"((R)[2]), "=r"((R)[3]) : "r"(addr))

__device__ __forceinline__ void mma_bf16(float* d, const uint32_t* a,
                                         uint32_t b0, uint32_t b1) {
    asm volatile(
        "mma.sync.aligned.m16n8k16.row.col.f32.bf16.bf16.f32 "
        "{%0,%1,%2,%3}, {%4,%5,%6,%7}, {%8,%9}, {%0,%1,%2,%3};"
        : "+f"(d[0]), "+f"(d[1]), "+f"(d[2]), "+f"(d[3])
        : "r"(a[0]), "r"(a[1]), "r"(a[2]), "r"(a[3]), "r"(b0), "r"(b1));
}
__device__ __forceinline__ void mma_tf32(float* d, const uint32_t* a,
                                         uint32_t b0, uint32_t b1) {
    asm volatile(
        "mma.sync.aligned.m16n8k8.row.col.f32.tf32.tf32.f32 "
        "{%0,%1,%2,%3}, {%4,%5,%6,%7}, {%8,%9}, {%0,%1,%2,%3};"
        : "+f"(d[0]), "+f"(d[1]), "+f"(d[2]), "+f"(d[3])
        : "r"(a[0]), "r"(a[1]), "r"(a[2]), "r"(a[3]), "r"(b0), "r"(b1));
}

// ---------------------------------------------------------------------------
// up/down bf16 GEMM (R6 config): D[128,128] = A[128,K] @ B^T.
// MODE 0: up     A=g_xh, B=g_uwT, out -> g_h (bf16, relu^2)
// MODE 1: down   A=g_h,  B=g_dwT, out: C += D
// ---------------------------------------------------------------------------
template <int MODE>
__global__ __launch_bounds__(256, 2) void gemm_tc(float* __restrict__ C)
{
    constexpr int K  = (MODE == 1) ? INTER : HID;
    constexpr int KT = K / BK;

    extern __shared__ char smem[];
    const uint32_t sb = smem_u32(smem);

    const int tid  = threadIdx.x;
    const int wid  = tid >> 5;
    const int lane = tid & 31;
    const int wm   = wid & 3;
    const int wn   = wid >> 2;
    const int mBase = blockIdx.y * BM;
    const int nBase = blockIdx.x * BN;

    const int lrow = tid >> 3;
    const int lseg = tid & 7;
    const uint32_t lsw = (uint32_t)((lseg ^ (lrow & 7)) << 4);

    auto load_chunk = [&](int q) {
        const __nv_bfloat16 *Ap = (MODE == 0) ? g_xh : g_h;
        const __nv_bfloat16 *Bp = (MODE == 0) ? g_uwT : g_dwT;
        const uint32_t base = sb + (q % NSTAGES) * STG_BYTES;
        const size_t k0 = (size_t)q * BK + lseg * 8;
#pragma unroll
        for (int i = 0; i < 4; i++) {
            const int row = lrow + i * 32;
            cp_async16(base + row * 128 + lsw,
                       Ap + (size_t)(mBase + row) * K + k0);
        }
#pragma unroll
        for (int i = 0; i < 4; i++) {
            const int row = lrow + i * 32;
            cp_async16(base + BM * 128 + row * 128 + lsw,
                       Bp + (size_t)(nBase + row) * K + k0);
        }
    };

    float acc[2][8][4];
#pragma unroll
    for (int i = 0; i < 2; i++)
#pragma unroll
        for (int j = 0; j < 8; j++)
#pragma unroll
            for (int v = 0; v < 4; v++) acc[i][j][v] = 0.f;

    const int g  = lane >> 3;
    const int r8 = lane & 7;
    const int rowA0 = wm * 32 + r8 + (g & 1) * 8;
    const int rowB0 = wn * 64 + r8 + (g & 1) * 8;
    const int segHi = g >> 1;

    load_chunk(0); cp_commit();
    load_chunk(1); cp_commit();

    for (int c = 0; c < KT; ++c) {
        cp_wait<1>();
        __syncthreads();
        if (c + 2 < KT) load_chunk(c + 2);
        cp_commit();

        const uint32_t aB = sb + (c % NSTAGES) * STG_BYTES;
        const uint32_t bB = aB + BM * 128;
#pragma unroll
        for (int k16 = 0; k16 < 4; k16++) {
            const int seg = k16 * 2 + segHi;
            uint32_t A0[4], A1[4], Bf[4][4];
            {
                const int row = rowA0;
                LDSM4(A0, aB + row * 128 + ((seg ^ (row & 7)) << 4));
            }
            {
                const int row = rowA0 + 16;
                LDSM4(A1, aB + row * 128 + ((seg ^ (row & 7)) << 4));
            }
#pragma unroll
            for (int bt = 0; bt < 4; bt++) {
                const int row = rowB0 + bt * 16;
                LDSM4(Bf[bt], bB + row * 128 + ((seg ^ (row & 7)) << 4));
            }
#pragma unroll
            for (int nj = 0; nj < 8; nj++) {
                const uint32_t b0 = Bf[nj >> 1][nj & 1];
                const uint32_t b1 = Bf[nj >> 1][2 + (nj & 1)];
                mma_bf16(acc[0][nj], A0, b0, b1);
                mma_bf16(acc[1][nj], A1, b0, b1);
            }
        }
    }

    const int rl = lane >> 2;
    const int cl = (lane & 3) * 2;
#pragma unroll
    for (int mi = 0; mi < 2; mi++) {
        const int r0 = mBase + wm * 32 + mi * 16 + rl;
#pragma unroll
        for (int nj = 0; nj < 8; nj++) {
            const int cc = nBase + wn * 64 + nj * 8 + cl;
            const float* d = acc[mi][nj];
            if (MODE == 0) {
                float a0 = d[0] > 0.f ? d[0] * d[0] : 0.f;
                float a1 = d[1] > 0.f ? d[1] * d[1] : 0.f;
                float a2 = d[2] > 0.f ? d[2] * d[2] : 0.f;
                float a3 = d[3] > 0.f ? d[3] * d[3] : 0.f;
                __nv_bfloat162 p0 = __floats2bfloat162_rn(a0, a1);
                __nv_bfloat162 p1 = __floats2bfloat162_rn(a2, a3);
                *(uint32_t*)(g_h + (size_t)r0 * INTER + cc)       = *(uint32_t*)&p0;
                *(uint32_t*)(g_h + (size_t)(r0 + 8) * INTER + cc) = *(uint32_t*)&p1;
            } else {
                float2* p0 = (float2*)(C + (size_t)r0 * HID + cc);
                float2* p1 = (float2*)(C + (size_t)(r0 + 8) * HID + cc);
                float2 v0 = *p0, v1 = *p1;
                v0.x += d[0]; v0.y += d[1];
                v1.x += d[2]; v1.y += d[3];
                *p0 = v0; *p1 = v1;
            }
        }
    }
}

// ---------------------------------------------------------------------------
// Expert GEMM, single-pass tf32: D = x @ ewT^T, C = D * g_scale[row].
// A = x fp32 (HW-truncated to tf32), B = g_ewT (tf32-pre-rounded fp32).
// ldmatrix-for-tf32: each 8x8 b16 matrix == 8 rows x 4 tf32 words, whose
// lane->word map equals the tf32 fragment layout.
//   A frag (m16k8): a0=A[g][t] a1=A[g+8][t] a2=A[g][t+4] a3=A[g+8][t+4]
//     lanes 0-7:M0(row r8, +0B) 8-15:M1(r8+8,+0B) 16-23:M2(r8,+16B) 24-31:M3(r8+8,+16B)
//   B frag (k8n8):  b0=B[t][g] b1=B[t+4][g]; storage [n][k]:
//     lanes 0-7:M0(n r8,+0B) 8-15:M1(r8,+16B) 16-23:M2(r8+8,+0B) 24-31:M3(r8+8,+16B)
//     -> regs (b0,b1) of n-octet0, (b0,b1) of n-octet1
// ---------------------------------------------------------------------------
__global__ __launch_bounds__(256, 2) void gemm_expert(
    float* __restrict__ C, const float* __restrict__ x)
{
    constexpr int K  = HID;
    constexpr int KT = K / EBK;            // 64 chunks of 32 fp32 (128B rows)

    extern __shared__ char smem[];
    const uint32_t sb = smem_u32(smem);

    const int tid  = threadIdx.x;
    const int wid  = tid >> 5;
    const int lane = tid & 31;
    const int wm   = wid & 3;
    const int wn   = wid >> 2;
    const int mBase = blockIdx.y * BM;
    const int nBase = blockIdx.x * BN;

    const int lrow = tid >> 3;
    const int lseg = tid & 7;
    const uint32_t lsw = (uint32_t)((lseg ^ (lrow & 7)) << 4);

    auto load_chunk = [&](int q) {
        const uint32_t base = sb + (q % 3) * ESTG;
        const size_t k0 = (size_t)q * EBK + lseg * 4;   // fp32 elems, 16B = 4
#pragma unroll
        for (int i = 0; i < 4; i++) {
            const int row = lrow + i * 32;
            cp_async16(base + row * 128 + lsw,
                       x + (size_t)(mBase + row) * K + k0);
        }
#pragma unroll
        for (int i = 0; i < 4; i++) {
            const int row = lrow + i * 32;
            cp_async16(base + BM * 128 + row * 128 + lsw,
                       g_ewT + (size_t)(nBase + row) * K + k0);
        }
    };

    float acc[2][8][4];
#pragma unroll
    for (int i = 0; i < 2; i++)
#pragma unroll
        for (int j = 0; j < 8; j++)
#pragma unroll
            for (int v = 0; v < 4; v++) acc[i][j][v] = 0.f;

    const int g2 = lane >> 3;
    const int r8 = lane & 7;
    // A: row += (g2&1)*8, seg += (g2>>1)
    const int rowA0 = wm * 32 + r8 + (g2 & 1) * 8;
    const int segA  = g2 >> 1;
    // B: row += (g2>>1)*8, seg += (g2&1)
    const int rowB0 = wn * 64 + r8 + (g2 >> 1) * 8;
    const int segB  = g2 & 1;

    load_chunk(0); cp_commit();
    load_chunk(1); cp_commit();

    for (int c = 0; c < KT; ++c) {
        cp_wait<1>();
        __syncthreads();
        if (c + 2 < KT) load_chunk(c + 2);
        cp_commit();

        const uint32_t aB = sb + (c % 3) * ESTG;
        const uint32_t bB = aB + BM * 128;
#pragma unroll
        for (int k8 = 0; k8 < 4; k8++) {        // 4 x K=8 steps per 32-chunk
            const int sgA = k8 * 2 + segA;
            const int sgB = k8 * 2 + segB;
            uint32_t A0[4], A1[4], Bf[4][4];
            {
                const int row = rowA0;
                LDSM4(A0, aB + row * 128 + ((sgA ^ (row & 7)) << 4));
            }
            {
                const int row = rowA0 + 16;
                LDSM4(A1, aB + row * 128 + ((sgA ^ (row & 7)) << 4));
            }
#pragma unroll
            for (int bt = 0; bt < 4; bt++) {
                const int row = rowB0 + bt * 16;
                LDSM4(Bf[bt], bB + row * 128 + ((sgB ^ (row & 7)) << 4));
            }
#pragma unroll
            for (int nj = 0; nj < 8; nj++) {
                const uint32_t b0 = Bf[nj >> 1][(nj & 1) * 2];
                const uint32_t b1 = Bf[nj >> 1][(nj & 1) * 2 + 1];
                mma_tf32(acc[0][nj], A0, b0, b1);
                mma_tf32(acc[1][nj], A1, b0, b1);
            }
        }
    }

    // ---- epilogue: C = acc * scale[row] ----
    const int rl = lane >> 2;
    const int cl = (lane & 3) * 2;
#pragma unroll
    for (int mi = 0; mi < 2; mi++) {
        const int r0 = mBase + wm * 32 + mi * 16 + rl;
        const float s0 = g_scale[r0];
        const float s8 = g_scale[r0 + 8];
#pragma unroll
        for (int nj = 0; nj < 8; nj++) {
            const int cc = nBase + wn * 64 + nj * 8 + cl;
            const float* d = acc[mi][nj];
            *(float2*)(C + (size_t)r0 * HID + cc)       = make_float2(d[0] * s0, d[1] * s0);
            *(float2*)(C + (size_t)(r0 + 8) * HID + cc) = make_float2(d[2] * s8, d[3] * s8);
        }
    }
}

// ---------------------------------------------------------------------------
// x -> bf16 (for up GEMM)
// ---------------------------------------------------------------------------
__global__ __launch_bounds__(256) void cvt_x_kernel(const float* __restrict__ x)
{
    const size_t i = ((size_t)blockIdx.x * 256 + threadIdx.x) * 4;
    float4 v = *(const float4*)(x + i);
    __nv_bfloat16 h[4];
#pragma unroll
    for (int j = 0; j < 4; j++) h[j] = __float2bfloat16_rn((&v.x)[j]);
    *(uint2*)(g_xh + i) = *(uint2*)h;
}

// ---------------------------------------------------------------------------
// transpose + convert: WHICH 0: g_uwT bf16  1: g_dwT bf16  2: g_ewT tf32-fp32
// ---------------------------------------------------------------------------
template <int WHICH>
__global__ __launch_bounds__(256) void trans_cvt_kernel(const float* __restrict__ src, int R, int C)
{
    __shared__ float t[32][33];
    const int bx = blockIdx.x * 32, by = blockIdx.y * 32;
    const int tx = threadIdx.x & 31, ty = threadIdx.x >> 5;
#pragma unroll
    for (int j = 0; j < 32; j += 8)
        t[ty + j][tx] = src[(size_t)(by + ty + j) * C + bx + tx];
    __syncthreads();
#pragma unroll
    for (int j = 0; j < 32; j += 8) {
        const float v = t[tx][ty + j];
        const size_t o = (size_t)(bx + ty + j) * R + by + tx;
        if (WHICH == 0) g_uwT[o] = __float2bfloat16_rn(v);
        else if (WHICH == 1) g_dwT[o] = __float2bfloat16_rn(v);
        else {
            uint32_t tb;
            asm("cvt.rna.tf32.f32 %0, %1;" : "=r"(tb) : "f"(v));
            ((uint32_t*)g_ewT)[o] = tb;
        }
    }
}

// ---------------------------------------------------------------------------
// Routing: scale = sum of top-2 of x @ gate_w (fp32)
// ---------------------------------------------------------------------------
__global__ __launch_bounds__(256) void routing_kernel(
    const float* __restrict__ x, const float* __restrict__ gate_w)
{
    __shared__ float xs[8][32][33];
    __shared__ float gws[256];
    const int w = threadIdx.x >> 5, lane = threadIdx.x & 31;
    const int t0 = blockIdx.x * 256;
    float acc[NEXP];
#pragma unroll
    for (int e = 0; e < NEXP; e++) acc[e] = 0.f;
    for (int c = 0; c < HID / 32; ++c) {
        const int k0 = c * 32;
#pragma unroll 8
        for (int r = 0; r < 32; ++r)
            xs[w][r][lane] = x[(size_t)(t0 + w * 32 + r) * HID + k0 + lane];
        gws[threadIdx.x] = gate_w[c * 256 + threadIdx.x];
        __syncthreads();
#pragma unroll
        for (int kk = 0; kk < 32; ++kk) {
            const float xv = xs[w][lane][kk];
            const float* g = &gws[kk * NEXP];
#pragma unroll
            for (int e = 0; e < NEXP; e++) acc[e] += xv * g[e];
        }
        __syncthreads();
    }
    float m1 = -1e30f, m2 = -1e30f;
#pragma unroll
    for (int e = 0; e < NEXP; e++) {
        const float v = acc[e];
        if (v > m1) { m2 = m1; m1 = v; } else if (v > m2) { m2 = v; }
    }
    g_scale[t0 + w * 32 + lane] = m1 + m2;
}

// ---------------------------------------------------------------------------
// LayerNorm in place
// ---------------------------------------------------------------------------
__global__ __launch_bounds__(256) void ln_kernel(
    float* __restrict__ y, const float* __restrict__ gamma, const float* __restrict__ beta)
{
    __shared__ float ssum[8], ssum2[8];
    float* row = y + (size_t)blockIdx.x * HID;
    const int base = threadIdx.x * 8;
    float4 v0 = *(float4*)(row + base);
    float4 v1 = *(float4*)(row + base + 4);
    float vals[8] = {v0.x, v0.y, v0.z, v0.w, v1.x, v1.y, v1.z, v1.w};
    float s = 0.f, s2 = 0.f;
#pragma unroll
    for (int i = 0; i < 8; i++) { s += vals[i]; s2 += vals[i] * vals[i]; }
#pragma unroll
    for (int off = 16; off > 0; off >>= 1) {
        s  += __shfl_xor_sync(0xffffffff, s,  off);
        s2 += __shfl_xor_sync(0xffffffff, s2, off);
    }
    const int warp = threadIdx.x >> 5, lane = threadIdx.x & 31;
    if (lane == 0) { ssum[warp] = s; ssum2[warp] = s2; }
    __syncthreads();
    s = 0.f; s2 = 0.f;
#pragma unroll
    for (int i = 0; i < 8; i++) { s += ssum[i]; s2 += ssum2[i]; }
    const float mu = s * (1.f / HID);
    const float rstd = rsqrtf(s2 * (1.f / HID) - mu * mu + LN_EPS);
    float4 g0 = *(const float4*)(gamma + base);
    float4 g1 = *(const float4*)(gamma + base + 4);
    float4 b0 = *(const float4*)(beta + base);
    float4 b1 = *(const float4*)(beta + base + 4);
    float gs[8] = {g0.x, g0.y, g0.z, g0.w, g1.x, g1.y, g1.z, g1.w};
    float bs[8] = {b0.x, b0.y, b0.z, b0.w, b1.x, b1.y, b1.z, b1.w};
    float o[8];
#pragma unroll
    for (int i = 0; i < 8; i++) o[i] = (vals[i] - mu) * rstd * gs[i] + bs[i];
    *(float4*)(row + base)     = make_float4(o[0], o[1], o[2], o[3]);
    *(float4*)(row + base + 4) = make_float4(o[4], o[5], o[6], o[7]);
}

// ---------------------------------------------------------------------------
extern "C" void kernel_launch(void* const* d_in, const int* in_sizes, int n_in,
                              void* d_out, int out_size)
{
    const float* x        = (const float*)d_in[0];
    const float* gate_w   = (const float*)d_in[1];
    const float* up_w     = (const float*)d_in[2];
    const float* down_w   = (const float*)d_in[3];
    const float* expert_w = (const float*)d_in[4];
    const float* gamma    = (const float*)d_in[5];
    const float* beta     = (const float*)d_in[6];
    float* out = (float*)d_out;

    static bool attr_done = false;
    if (!attr_done) {
        cudaFuncSetAttribute(gemm_tc<0>, cudaFuncAttributeMaxDynamicSharedMemorySize, SMEM_TOTAL);
        cudaFuncSetAttribute(gemm_tc<1>, cudaFuncAttributeMaxDynamicSharedMemorySize, SMEM_TOTAL);
        cudaFuncSetAttribute(gemm_expert, cudaFuncAttributeMaxDynamicSharedMemorySize, ESMEM_TOTAL);
        attr_done = true;
    }

    // operand conversions
    cvt_x_kernel<<<(NTOK * HID) / 1024, 256>>>(x);
    trans_cvt_kernel<0><<<dim3(INTER / 32, HID / 32), 256>>>(up_w,     HID,   INTER);
    trans_cvt_kernel<1><<<dim3(HID / 32, INTER / 32), 256>>>(down_w,   INTER, HID);
    trans_cvt_kernel<2><<<dim3(HID / 32, HID / 32),   256>>>(expert_w, HID,   HID);
    // routing (fp32)
    routing_kernel<<<NTOK / 256, 256>>>(x, gate_w);
    // expert (single-pass tf32): out = scale * (x @ expert_w)
    gemm_expert<<<dim3(HID / BN, NTOK / BM), 256, ESMEM_TOTAL>>>(out, x);
    // up: g_h = relu(x @ up_w)^2
    gemm_tc<0><<<dim3(INTER / BN, NTOK / BM), 256, SMEM_TOTAL>>>(nullptr);
    // down: out += g_h @ down_w
    gemm_tc<1><<<dim3(HID / BN, NTOK / BM), 256, SMEM_TOTAL>>>(out);
    // layernorm
    ln_kernel<<<NTOK, 256>>>(out, gamma, beta);
}